// round 8
// baseline (speedup 1.0000x reference)
#include <cuda_runtime.h>

// 3D Haar DWT: x (2,32,64,128,128) fp32 -> 8 subbands each (2,32,32,64,64),
// order (LLL,LLH,LHL,LHH,HLL,HLH,HHL,HHH).
// R7: persistent grid-stride kernel (one wave: 148 SMs x 8 blocks) on top of
// the best-measured config (v8 256-bit loads, v4 stores, 8-w-inputs/thread).
// Removes the multi-wave transition/tail term. All cache hints dropped
// (measured no-ops: identical DRAM traffic in R2/R4/R5/R6).

constexpr int IN_D = 64, IN_H = 128, IN_W = 128;
constexpr int OD = 32, OP = 64, OQ = 64;
constexpr int NC = 64;                         // N*C
constexpr long long SUB = (long long)NC * OD * OP * OQ;

constexpr int NBLOCKS = 148 * 8;               // one full wave at 8 CTAs/SM
constexpr int NTHREADS = NBLOCKS * 256;
constexpr int TOTAL_ITEMS = NC * OD * OP * (OQ / 4);  // 2,097,152 work items

// 256-bit load of 8 consecutive floats.
__device__ __forceinline__ void ld8(const float* p, float4& u, float4& v) {
    unsigned r0, r1, r2, r3, r4, r5, r6, r7;
    asm volatile(
        "ld.global.nc.v8.b32 {%0,%1,%2,%3,%4,%5,%6,%7}, [%8];"
        : "=r"(r0), "=r"(r1), "=r"(r2), "=r"(r3),
          "=r"(r4), "=r"(r5), "=r"(r6), "=r"(r7)
        : "l"(p));
    u = make_float4(__uint_as_float(r0), __uint_as_float(r1),
                    __uint_as_float(r2), __uint_as_float(r3));
    v = make_float4(__uint_as_float(r4), __uint_as_float(r5),
                    __uint_as_float(r6), __uint_as_float(r7));
}

__device__ __forceinline__ float4 f4add(float4 a, float4 b) {
    return make_float4(a.x + b.x, a.y + b.y, a.z + b.z, a.w + b.w);
}
__device__ __forceinline__ float4 f4sub(float4 a, float4 b) {
    return make_float4(a.x - b.x, a.y - b.y, a.z - b.z, a.w - b.w);
}
__device__ __forceinline__ float4 f4scale(float4 a, float s) {
    return make_float4(a.x * s, a.y * s, a.z * s, a.w * s);
}

struct WPair { float4 lo, hi; };
__device__ __forceinline__ WPair wsplit(float4 u, float4 v) {
    WPair r;
    r.lo = make_float4(u.x + u.y, u.z + u.w, v.x + v.y, v.z + v.w);
    r.hi = make_float4(u.x - u.y, u.z - u.w, v.x - v.y, v.z - v.w);
    return r;
}

__global__ void __launch_bounds__(256) dwt3d_haar_kernel(
    const float* __restrict__ x, float* __restrict__ out)
{
    const long long dstride = (long long)IN_H * IN_W;
    const float s = 0.3535533905932738f;  // (1/sqrt(2))^3
    const long long sub4 = SUB / 4;

    for (int idx = blockIdx.x * 256 + threadIdx.x; idx < TOTAL_ITEMS;
         idx += NTHREADS) {
        // decode: q4 (16), p (64), r (32), nc (64)
        int q4 = idx & 15;
        int t  = idx >> 4;
        int p  = t & 63;
        t >>= 6;
        int r  = t & 31;
        int nc = t >> 5;

        const float* base = x
            + (((long long)nc * IN_D + 2 * r) * IN_H + 2 * p) * IN_W
            + q4 * 8;

        float4 a0, a1, b0, b1, c0, c1, d0, d1;
        ld8(base,                  a0, a1);  // d=0, h=0
        ld8(base + IN_W,           b0, b1);  // d=0, h=1
        ld8(base + dstride,        c0, c1);  // d=1, h=0
        ld8(base + dstride + IN_W, d0, d1);  // d=1, h=1

        // Stage 1: w butterflies
        WPair w00 = wsplit(a0, a1);
        WPair w01 = wsplit(b0, b1);
        WPair w10 = wsplit(c0, c1);
        WPair w11 = wsplit(d0, d1);

        // Stage 2: h butterflies
        float4 d0_ll = f4add(w00.lo, w01.lo);
        float4 d0_lh = f4add(w00.hi, w01.hi);
        float4 d0_hl = f4sub(w00.lo, w01.lo);
        float4 d0_hh = f4sub(w00.hi, w01.hi);
        float4 d1_ll = f4add(w10.lo, w11.lo);
        float4 d1_lh = f4add(w10.hi, w11.hi);
        float4 d1_hl = f4sub(w10.lo, w11.lo);
        float4 d1_hh = f4sub(w10.hi, w11.hi);

        // Stage 3: d butterflies + scale, store to 8 subbands
        long long o = (((long long)nc * OD + r) * OP + p) * OQ + q4 * 4;
        float4* outp = (float4*)(out + o);

        outp[0 * sub4] = f4scale(f4add(d0_ll, d1_ll), s);
        outp[1 * sub4] = f4scale(f4add(d0_lh, d1_lh), s);
        outp[2 * sub4] = f4scale(f4add(d0_hl, d1_hl), s);
        outp[3 * sub4] = f4scale(f4add(d0_hh, d1_hh), s);
        outp[4 * sub4] = f4scale(f4sub(d0_ll, d1_ll), s);
        outp[5 * sub4] = f4scale(f4sub(d0_lh, d1_lh), s);
        outp[6 * sub4] = f4scale(f4sub(d0_hl, d1_hl), s);
        outp[7 * sub4] = f4scale(f4sub(d0_hh, d1_hh), s);
    }
}

extern "C" void kernel_launch(void* const* d_in, const int* in_sizes, int n_in,
                              void* d_out, int out_size) {
    const float* x = (const float*)d_in[0];
    float* out = (float*)d_out;

    dwt3d_haar_kernel<<<NBLOCKS, 256>>>(x, out);
}

// round 10
// speedup vs baseline: 1.0546x; 1.0546x over previous
#include <cuda_runtime.h>

// 3D Haar DWT: x (2,32,64,128,128) fp32 -> 8 subbands each (2,32,32,64,64),
// order (LLL,LLH,LHL,LHH,HLL,HLH,HHL,HHH).
//
// FINAL (R8 = best-measured config, R4 shape, hints stripped):
//   - one thread per 4 output columns (8 input w-values)
//   - 4x 256-bit v8 loads (one per input row), 8x 128-bit v4 stores
//   - 8192 blocks x 256 threads, oversubscribed launch (best memory-system
//     pipelining: fresh load-heavy CTAs overlap draining store-heavy ones)
//
// Session evidence: kernel is pinned at the HBM3e mixed 50/50 R/W turnaround
// ceiling (~6.3 TB/s = ~79% of spec). Falsified levers (all neutral):
// cache hints (stcs/evict_last/evict_first/partial-pin — identical DRAM
// bytes), deeper per-thread MLP, 256-bit stores, occupancy 29-53%.
// Persistent single-wave launch regressed (-5%): grid-stride serializes
// load->store->load chains per thread.

constexpr int IN_D = 64, IN_H = 128, IN_W = 128;
constexpr int OD = 32, OP = 64, OQ = 64;
constexpr int NC = 64;                         // N*C
constexpr long long SUB = (long long)NC * OD * OP * OQ;

// 256-bit load of 8 consecutive floats.
__device__ __forceinline__ void ld8(const float* p, float4& u, float4& v) {
    unsigned r0, r1, r2, r3, r4, r5, r6, r7;
    asm volatile(
        "ld.global.nc.v8.b32 {%0,%1,%2,%3,%4,%5,%6,%7}, [%8];"
        : "=r"(r0), "=r"(r1), "=r"(r2), "=r"(r3),
          "=r"(r4), "=r"(r5), "=r"(r6), "=r"(r7)
        : "l"(p));
    u = make_float4(__uint_as_float(r0), __uint_as_float(r1),
                    __uint_as_float(r2), __uint_as_float(r3));
    v = make_float4(__uint_as_float(r4), __uint_as_float(r5),
                    __uint_as_float(r6), __uint_as_float(r7));
}

__device__ __forceinline__ float4 f4add(float4 a, float4 b) {
    return make_float4(a.x + b.x, a.y + b.y, a.z + b.z, a.w + b.w);
}
__device__ __forceinline__ float4 f4sub(float4 a, float4 b) {
    return make_float4(a.x - b.x, a.y - b.y, a.z - b.z, a.w - b.w);
}
__device__ __forceinline__ float4 f4scale(float4 a, float s) {
    return make_float4(a.x * s, a.y * s, a.z * s, a.w * s);
}

struct WPair { float4 lo, hi; };
__device__ __forceinline__ WPair wsplit(float4 u, float4 v) {
    WPair r;
    r.lo = make_float4(u.x + u.y, u.z + u.w, v.x + v.y, v.z + v.w);
    r.hi = make_float4(u.x - u.y, u.z - u.w, v.x - v.y, v.z - v.w);
    return r;
}

__global__ void __launch_bounds__(256) dwt3d_haar_kernel(
    const float* __restrict__ x, float* __restrict__ out)
{
    int idx = blockIdx.x * 256 + threadIdx.x;
    // decode: q4 (16), p (64), r (32), nc (64)
    int q4 = idx & 15;
    int t  = idx >> 4;
    int p  = t & 63;
    t >>= 6;
    int r  = t & 31;
    int nc = t >> 5;

    const long long dstride = (long long)IN_H * IN_W;
    const float* base = x
        + (((long long)nc * IN_D + 2 * r) * IN_H + 2 * p) * IN_W
        + q4 * 8;

    float4 a0, a1, b0, b1, c0, c1, d0, d1;
    ld8(base,                  a0, a1);  // d=0, h=0
    ld8(base + IN_W,           b0, b1);  // d=0, h=1
    ld8(base + dstride,        c0, c1);  // d=1, h=0
    ld8(base + dstride + IN_W, d0, d1);  // d=1, h=1

    // Stage 1: w-axis butterflies
    WPair w00 = wsplit(a0, a1);
    WPair w01 = wsplit(b0, b1);
    WPair w10 = wsplit(c0, c1);
    WPair w11 = wsplit(d0, d1);

    // Stage 2: h-axis butterflies
    float4 d0_ll = f4add(w00.lo, w01.lo);
    float4 d0_lh = f4add(w00.hi, w01.hi);
    float4 d0_hl = f4sub(w00.lo, w01.lo);
    float4 d0_hh = f4sub(w00.hi, w01.hi);
    float4 d1_ll = f4add(w10.lo, w11.lo);
    float4 d1_lh = f4add(w10.hi, w11.hi);
    float4 d1_hl = f4sub(w10.lo, w11.lo);
    float4 d1_hh = f4sub(w10.hi, w11.hi);

    // Stage 3: d-axis butterflies + scale
    const float s = 0.3535533905932738f;  // (1/sqrt(2))^3

    long long o = (((long long)nc * OD + r) * OP + p) * OQ + q4 * 4;
    float4* outp = (float4*)(out + o);
    const long long sub4 = SUB / 4;

    outp[0 * sub4] = f4scale(f4add(d0_ll, d1_ll), s);
    outp[1 * sub4] = f4scale(f4add(d0_lh, d1_lh), s);
    outp[2 * sub4] = f4scale(f4add(d0_hl, d1_hl), s);
    outp[3 * sub4] = f4scale(f4add(d0_hh, d1_hh), s);
    outp[4 * sub4] = f4scale(f4sub(d0_ll, d1_ll), s);
    outp[5 * sub4] = f4scale(f4sub(d0_lh, d1_lh), s);
    outp[6 * sub4] = f4scale(f4sub(d0_hl, d1_hl), s);
    outp[7 * sub4] = f4scale(f4sub(d0_hh, d1_hh), s);
}

extern "C" void kernel_launch(void* const* d_in, const int* in_sizes, int n_in,
                              void* d_out, int out_size) {
    const float* x = (const float*)d_in[0];
    float* out = (float*)d_out;

    const int total = NC * OD * OP * (OQ / 4);  // 2,097,152 threads
    dwt3d_haar_kernel<<<total / 256, 256>>>(x, out);
}